// round 4
// baseline (speedup 1.0000x reference)
#include <cuda_runtime.h>
#include <math.h>

// ---------------------------------------------------------------------------
// GPT-2 small forward pass. fp32 everywhere; GEMMs use split-tf32 (3xTF32)
// tensor-core mma.sync for ~fp32 accuracy at tensor-core speed.
// ---------------------------------------------------------------------------

namespace {
constexpr int B_  = 4;
constexpr int T_  = 1024;
constexpr int C_  = 768;
constexpr int H_  = 12;
constexpr int HS_ = 64;
constexpr int L_  = 12;
constexpr int V_  = 32000;
constexpr int BT_ = B_ * T_;
constexpr int C4_ = 4 * C_;
}

// Scratch (no cudaMalloc allowed -> device globals)
__device__ float g_x [BT_ * C_];
__device__ float g_h [BT_ * C_];
__device__ float g_q [BT_ * C_];
__device__ float g_k [BT_ * C_];
__device__ float g_v [BT_ * C_];
__device__ float g_o [BT_ * C_];
__device__ float g_a1[BT_ * C4_];
__device__ float g_att[(size_t)B_ * H_ * T_ * T_];

// ---------------------------------------------------------------------------
// tf32 helpers
// ---------------------------------------------------------------------------
__device__ __forceinline__ void tf32_split(float x, unsigned &hi, unsigned &lo) {
    unsigned h;
    asm("cvt.rna.tf32.f32 %0, %1;" : "=r"(h) : "f"(x));
    float hf = __uint_as_float(h);
    float l  = x - hf;                 // exact in fp32
    unsigned lu;
    asm("cvt.rna.tf32.f32 %0, %1;" : "=r"(lu) : "f"(l));
    hi = h; lo = lu;
}

__device__ __forceinline__ void mma_tf32(float* d, const unsigned* a, const unsigned* b) {
    asm volatile(
        "mma.sync.aligned.m16n8k8.row.col.f32.tf32.tf32.f32 "
        "{%0,%1,%2,%3}, {%4,%5,%6,%7}, {%8,%9}, {%0,%1,%2,%3};"
        : "+f"(d[0]), "+f"(d[1]), "+f"(d[2]), "+f"(d[3])
        : "r"(a[0]), "r"(a[1]), "r"(a[2]), "r"(a[3]),
          "r"(b[0]), "r"(b[1]));
}

// ---------------------------------------------------------------------------
// GEMM: C = alpha * A@B (+bias) (+gelu) (+resid)
//   A: [M,K] row-major, lda
//   B: if !transB: [K,N] row-major, ldb.  if transB: [N,K] row-major (A@B^T).
//   batched over gridDim.z: offsets = (bz/nH)*s?b + (bz%nH)*s?h
// Tile 128x128x16, 256 threads (8 warps: 4 in M x 2 in N, each 32x64).
// All M are multiples of 128, all K multiples of 16; only N needs guarding
// (the attention AV GEMM has N=64).
// ---------------------------------------------------------------------------
__global__ void __launch_bounds__(256)
gemm_tf32(const float* __restrict__ A, const float* __restrict__ Bp,
          float* __restrict__ Cp,
          int M, int N, int K, int lda, int ldb, int ldc,
          long long sAb, long long sAh, long long sBb, long long sBh,
          long long sCb, long long sCh, int nH,
          const float* __restrict__ bias, const float* __restrict__ resid,
          float alpha, int doGelu, int transB)
{
    __shared__ float As[16][136];   // [k][m], stride 136 -> conflict-free frags
    __shared__ float Bs[16][136];   // [k][n]

    int bz = blockIdx.z;
    int bb = bz / nH, hh = bz - bb * nH;
    A  += bb * sAb + hh * sAh;
    Bp += bb * sBb + hh * sBh;
    Cp += bb * sCb + hh * sCh;
    const float* Rp = resid ? (resid + bb * sCb + hh * sCh) : (const float*)0;

    int m0   = blockIdx.y << 7;
    int n0   = blockIdx.x << 7;
    int tid  = threadIdx.x;
    int lane = tid & 31;
    int wid  = tid >> 5;
    int wm   = (wid & 3) << 5;   // 0,32,64,96
    int wn   = (wid >> 2) << 6;  // 0,64

    float acc[2][8][4];
    #pragma unroll
    for (int a = 0; a < 2; a++)
        #pragma unroll
        for (int b = 0; b < 8; b++)
            #pragma unroll
            for (int j = 0; j < 4; j++) acc[a][b][j] = 0.f;

    for (int k0 = 0; k0 < K; k0 += 16) {
        // ---- load A tile (128 x 16), scatter to [k][m] ----
        #pragma unroll
        for (int i = tid; i < 512; i += 256) {
            int m  = i >> 2;
            int kq = (i & 3) << 2;
            float4 vv = *(const float4*)(A + (size_t)(m0 + m) * lda + (k0 + kq));
            As[kq + 0][m] = vv.x; As[kq + 1][m] = vv.y;
            As[kq + 2][m] = vv.z; As[kq + 3][m] = vv.w;
        }
        // ---- load B tile -> Bs[k][n] ----
        if (transB) {
            #pragma unroll
            for (int i = tid; i < 512; i += 256) {
                int n  = i >> 2;
                int kq = (i & 3) << 2;
                float4 vv = make_float4(0.f, 0.f, 0.f, 0.f);
                if (n0 + n < N)
                    vv = *(const float4*)(Bp + (size_t)(n0 + n) * ldb + (k0 + kq));
                Bs[kq + 0][n] = vv.x; Bs[kq + 1][n] = vv.y;
                Bs[kq + 2][n] = vv.z; Bs[kq + 3][n] = vv.w;
            }
        } else {
            #pragma unroll
            for (int i = tid; i < 512; i += 256) {
                int kk = i >> 5;
                int nq = (i & 31) << 2;
                float4 vv = make_float4(0.f, 0.f, 0.f, 0.f);
                if (n0 + nq < N)
                    vv = *(const float4*)(Bp + (size_t)(k0 + kk) * ldb + (n0 + nq));
                *(float4*)&Bs[kk][nq] = vv;
            }
        }
        __syncthreads();

        // ---- compute: two k8 steps ----
        #pragma unroll
        for (int kk = 0; kk < 16; kk += 8) {
            unsigned ah[2][4], al[2][4], bh[8][2], bl[8][2];
            #pragma unroll
            for (int mt = 0; mt < 2; mt++) {
                int r  = wm + (mt << 4) + (lane >> 2);
                int ck = kk + (lane & 3);
                tf32_split(As[ck    ][r    ], ah[mt][0], al[mt][0]);
                tf32_split(As[ck    ][r + 8], ah[mt][1], al[mt][1]);
                tf32_split(As[ck + 4][r    ], ah[mt][2], al[mt][2]);
                tf32_split(As[ck + 4][r + 8], ah[mt][3], al[mt][3]);
            }
            #pragma unroll
            for (int nt = 0; nt < 8; nt++) {
                int cn = wn + (nt << 3) + (lane >> 2);
                int ck = kk + (lane & 3);
                tf32_split(Bs[ck    ][cn], bh[nt][0], bl[nt][0]);
                tf32_split(Bs[ck + 4][cn], bh[nt][1], bl[nt][1]);
            }
            #pragma unroll
            for (int mt = 0; mt < 2; mt++)
                #pragma unroll
                for (int nt = 0; nt < 8; nt++) {
                    mma_tf32(acc[mt][nt], ah[mt], bh[nt]);
                    mma_tf32(acc[mt][nt], ah[mt], bl[nt]);
                    mma_tf32(acc[mt][nt], al[mt], bh[nt]);
                }
        }
        __syncthreads();
    }

    // ---- epilogue ----
    #pragma unroll
    for (int mt = 0; mt < 2; mt++) {
        #pragma unroll
        for (int nt = 0; nt < 8; nt++) {
            int row = m0 + wm + (mt << 4) + (lane >> 2);
            int col = n0 + wn + (nt << 3) + ((lane & 3) << 1);
            #pragma unroll
            for (int j = 0; j < 4; j++) {
                int r = row + ((j & 2) ? 8 : 0);
                int c = col + (j & 1);
                if (c < N) {
                    float v2 = acc[mt][nt][j] * alpha;
                    if (bias) v2 += bias[c];
                    if (doGelu) v2 = 0.5f * v2 * (1.f + erff(v2 * 0.70710678118654752f));
                    if (Rp) v2 += Rp[(size_t)r * ldc + c];
                    Cp[(size_t)r * ldc + c] = v2;
                }
            }
        }
    }
}

// ---------------------------------------------------------------------------
// LayerNorm (biased variance, eps=1e-5): one block (256 thr) per row of C_
// ---------------------------------------------------------------------------
__global__ void layernorm_k(const float* __restrict__ x, const float* __restrict__ g,
                            const float* __restrict__ b, float* __restrict__ y)
{
    int row = blockIdx.x;
    const float* xr = x + (size_t)row * C_;
    float* yr       = y + (size_t)row * C_;
    int tid = threadIdx.x;
    float s = 0.f, s2 = 0.f;
    for (int c = tid; c < C_; c += 256) { float v = xr[c]; s += v; s2 += v * v; }
    __shared__ float shs[8], shs2[8];
    #pragma unroll
    for (int o = 16; o; o >>= 1) {
        s  += __shfl_xor_sync(0xffffffffu, s,  o);
        s2 += __shfl_xor_sync(0xffffffffu, s2, o);
    }
    if ((tid & 31) == 0) { shs[tid >> 5] = s; shs2[tid >> 5] = s2; }
    __syncthreads();
    float ts = 0.f, ts2 = 0.f;
    #pragma unroll
    for (int i = 0; i < 8; i++) { ts += shs[i]; ts2 += shs2[i]; }
    float mean = ts * (1.f / C_);
    float var  = ts2 * (1.f / C_) - mean * mean;
    float rstd = rsqrtf(var + 1e-5f);
    for (int c = tid; c < C_; c += 256)
        yr[c] = (xr[c] - mean) * rstd * g[c] + b[c];
}

// ---------------------------------------------------------------------------
// Causal softmax in place over att rows; one block (256 thr) per (b,h,q) row.
// Valid length = q+1; invalid tail written as 0 so AV GEMM can read all 1024.
// ---------------------------------------------------------------------------
__global__ void softmax_causal(float* __restrict__ att)
{
    int row = blockIdx.x;             // b*H*T + h*T + q
    int q   = row & (T_ - 1);
    float* a = att + (size_t)row * T_;
    int len = q + 1;
    int tid = threadIdx.x;
    __shared__ float sh[8];

    float mx = -3.0e38f;
    for (int c = tid; c < len; c += 256) mx = fmaxf(mx, a[c]);
    #pragma unroll
    for (int o = 16; o; o >>= 1) mx = fmaxf(mx, __shfl_xor_sync(0xffffffffu, mx, o));
    if ((tid & 31) == 0) sh[tid >> 5] = mx;
    __syncthreads();
    mx = sh[0];
    #pragma unroll
    for (int i = 1; i < 8; i++) mx = fmaxf(mx, sh[i]);
    __syncthreads();

    float s = 0.f;
    for (int c = tid; c < len; c += 256) s += expf(a[c] - mx);
    #pragma unroll
    for (int o = 16; o; o >>= 1) s += __shfl_xor_sync(0xffffffffu, s, o);
    if ((tid & 31) == 0) sh[tid >> 5] = s;
    __syncthreads();
    float tot = 0.f;
    #pragma unroll
    for (int i = 0; i < 8; i++) tot += sh[i];
    float inv = 1.f / tot;

    for (int c = tid; c < T_; c += 256)
        a[c] = (c < len) ? expf(a[c] - mx) * inv : 0.f;
}

// ---------------------------------------------------------------------------
// Embedding: x[b,t,:] = tok_emb[idx[b,t],:] + pos_emb[t,:]
// ---------------------------------------------------------------------------
__global__ void embed_k(const int* __restrict__ idx, const float* __restrict__ tok,
                        const float* __restrict__ pos, float* __restrict__ x)
{
    int r = blockIdx.x;
    int t = r & (T_ - 1);
    int token = idx[r];
    const float* te = tok + (size_t)token * C_;
    const float* pe = pos + (size_t)t * C_;
    float* xr = x + (size_t)r * C_;
    for (int c = threadIdx.x; c < C_; c += 256) xr[c] = te[c] + pe[c];
}

// ---------------------------------------------------------------------------
// Launch
// ---------------------------------------------------------------------------
extern "C" void kernel_launch(void* const* d_in, const int* in_sizes, int n_in,
                              void* d_out, int out_size)
{
    (void)in_sizes; (void)n_in; (void)out_size;
    const int*   idx = (const int*)d_in[0];
    const float* tok = (const float*)d_in[1];
    const float* pos = (const float*)d_in[2];
    const float* Wq  = (const float*)d_in[3];
    const float* Wk  = (const float*)d_in[4];
    const float* Wv  = (const float*)d_in[5];
    const float* Wp  = (const float*)d_in[6];
    const float* bp  = (const float*)d_in[7];
    const float* g1  = (const float*)d_in[8];
    const float* be1 = (const float*)d_in[9];
    const float* g2  = (const float*)d_in[10];
    const float* be2 = (const float*)d_in[11];
    const float* W1  = (const float*)d_in[12];
    const float* bb1 = (const float*)d_in[13];
    const float* W2  = (const float*)d_in[14];
    const float* bb2 = (const float*)d_in[15];
    const float* gf  = (const float*)d_in[16];
    const float* bf  = (const float*)d_in[17];
    const float* Wh  = (const float*)d_in[18];
    const float* bhd = (const float*)d_in[19];
    float* out = (float*)d_out;

    float *x, *h, *q, *k, *v, *o, *a1, *att;
    cudaGetSymbolAddress((void**)&x,   g_x);
    cudaGetSymbolAddress((void**)&h,   g_h);
    cudaGetSymbolAddress((void**)&q,   g_q);
    cudaGetSymbolAddress((void**)&k,   g_k);
    cudaGetSymbolAddress((void**)&v,   g_v);
    cudaGetSymbolAddress((void**)&o,   g_o);
    cudaGetSymbolAddress((void**)&a1,  g_a1);
    cudaGetSymbolAddress((void**)&att, g_att);

    const float att_scale = 0.03608439182435161f;  // 768^-0.5 (reference uses full C)

    embed_k<<<BT_, 256>>>(idx, tok, pos, x);

    dim3 gcc(C_ / 128, BT_ / 128, 1);
    dim3 gsc(T_ / 128, T_ / 128, B_ * H_);
    dim3 gav(1,        T_ / 128, B_ * H_);
    dim3 gf1(C4_ / 128, BT_ / 128, 1);

    for (int l = 0; l < L_; l++) {
        layernorm_k<<<BT_, 256>>>(x, g1 + l * C_, be1 + l * C_, h);

        gemm_tf32<<<gcc, 256>>>(h, Wq + (size_t)l * C_ * C_, q, BT_, C_, C_, C_, C_, C_,
                                0, 0, 0, 0, 0, 0, 1, (const float*)0, (const float*)0, 1.f, 0, 0);
        gemm_tf32<<<gcc, 256>>>(h, Wk + (size_t)l * C_ * C_, k, BT_, C_, C_, C_, C_, C_,
                                0, 0, 0, 0, 0, 0, 1, (const float*)0, (const float*)0, 1.f, 0, 0);
        gemm_tf32<<<gcc, 256>>>(h, Wv + (size_t)l * C_ * C_, v, BT_, C_, C_, C_, C_, C_,
                                0, 0, 0, 0, 0, 0, 1, (const float*)0, (const float*)0, 1.f, 0, 0);

        // scores: per (b,head) Q[1024,64] @ K^T -> att[1024,1024] (scaled)
        gemm_tf32<<<gsc, 256>>>(q, k, att, T_, T_, HS_, C_, C_, T_,
                                (long long)T_ * C_, (long long)HS_,
                                (long long)T_ * C_, (long long)HS_,
                                (long long)H_ * T_ * T_, (long long)T_ * T_, H_,
                                (const float*)0, (const float*)0, att_scale, 0, 1);

        softmax_causal<<<B_ * H_ * T_, 256>>>(att);

        // AV: P[1024,1024] @ V[1024,64] -> o
        gemm_tf32<<<gav, 256>>>(att, v, o, T_, HS_, T_, T_, C_, C_,
                                (long long)H_ * T_ * T_, (long long)T_ * T_,
                                (long long)T_ * C_, (long long)HS_,
                                (long long)T_ * C_, (long long)HS_, H_,
                                (const float*)0, (const float*)0, 1.f, 0, 0);

        // x = x + o @ Wproj + bproj
        gemm_tf32<<<gcc, 256>>>(o, Wp + (size_t)l * C_ * C_, x, BT_, C_, C_, C_, C_, C_,
                                0, 0, 0, 0, 0, 0, 1, bp + l * C_, x, 1.f, 0, 0);

        layernorm_k<<<BT_, 256>>>(x, g2 + l * C_, be2 + l * C_, h);

        // a1 = gelu(h @ W1 + b1)
        gemm_tf32<<<gf1, 256>>>(h, W1 + (size_t)l * C_ * C4_, a1, BT_, C4_, C_, C_, C4_, C4_,
                                0, 0, 0, 0, 0, 0, 1, bb1 + l * C4_, (const float*)0, 1.f, 1, 0);

        // x = x + a1 @ W2 + b2
        gemm_tf32<<<gcc, 256>>>(a1, W2 + (size_t)l * C4_ * C_, x, BT_, C_, C4_, C4_, C_, C_,
                                0, 0, 0, 0, 0, 0, 1, bb2 + l * C_, x, 1.f, 0, 0);
    }

    layernorm_k<<<BT_, 256>>>(x, gf, bf, h);

    dim3 ghd(V_ / 128, BT_ / 128, 1);
    gemm_tf32<<<ghd, 256>>>(h, Wh, out, BT_, V_, C_, C_, V_, V_,
                            0, 0, 0, 0, 0, 0, 1, bhd, (const float*)0, 1.f, 0, 0);
}

// round 5
// speedup vs baseline: 1.2412x; 1.2412x over previous
#include <cuda_runtime.h>
#include <math.h>

// ---------------------------------------------------------------------------
// GPT-2 small forward. fp32 activations; GEMMs use split-tf32 (3xTF32)
// mma.sync with hi/lo pre-split into smem and double-buffered tiles.
// ---------------------------------------------------------------------------

namespace {
constexpr int B_  = 4;
constexpr int T_  = 1024;
constexpr int C_  = 768;
constexpr int H_  = 12;
constexpr int HS_ = 64;
constexpr int L_  = 12;
constexpr int V_  = 32000;
constexpr int BT_ = B_ * T_;
constexpr int C4_ = 4 * C_;
constexpr int C3_ = 3 * C_;

constexpr int KT = 16;              // k per tile
constexpr int P  = 132;             // smem row pitch in float2 (conflict-free frags)
constexpr int STG = 2 * KT * P;     // float2 per stage (As + Bs)
constexpr size_t SMEM_BYTES = 2 * STG * sizeof(float2);   // 67584 B (2 stages)
}

// Scratch (no cudaMalloc -> device globals)
__device__ float g_x   [BT_ * C_];
__device__ float g_h   [BT_ * C_];
__device__ float g_qkv [BT_ * C3_];
__device__ float g_o   [BT_ * C_];
__device__ float g_a1  [BT_ * C4_];
__device__ float g_wcat[C_ * C3_];
__device__ float g_att [(size_t)B_ * H_ * T_ * T_];

// ---------------------------------------------------------------------------
// tf32 helpers
// ---------------------------------------------------------------------------
__device__ __forceinline__ float2 tf32_split2(float x) {
    unsigned h;
    asm("cvt.rna.tf32.f32 %0, %1;" : "=r"(h) : "f"(x));
    float hf = __uint_as_float(h);
    float l  = x - hf;                       // exact in fp32
    unsigned lu;
    asm("cvt.rna.tf32.f32 %0, %1;" : "=r"(lu) : "f"(l));
    return make_float2(hf, __uint_as_float(lu));
}

__device__ __forceinline__ void mma_tf32(float* d, const unsigned* a, const unsigned* b) {
    asm volatile(
        "mma.sync.aligned.m16n8k8.row.col.f32.tf32.tf32.f32 "
        "{%0,%1,%2,%3}, {%4,%5,%6,%7}, {%8,%9}, {%0,%1,%2,%3};"
        : "+f"(d[0]), "+f"(d[1]), "+f"(d[2]), "+f"(d[3])
        : "r"(a[0]), "r"(a[1]), "r"(a[2]), "r"(a[3]),
          "r"(b[0]), "r"(b[1]));
}

// ---------------------------------------------------------------------------
// GEMM: C = alpha * A@B (+bias) (+gelu) (+resid)
//   A: [M,K] row-major. B: !transB -> [K,N]; transB -> [N,K] (A@B^T).
//   Batched over gridDim.z via strides; nH splits bz into (batch, head).
// Tile 128x128xKT, 256 threads. MT=2: 8 warps as 4x2 (warp 32x64).
// MT=1 (for N<=64): 8 warps as 8x1 (warp 16x64), halves wasted MMAs.
// M % 128 == 0 and K % 16 == 0 always hold here; only N is guarded.
// Double-buffered smem stages hold pre-split (hi,lo) float2 operands.
// ---------------------------------------------------------------------------
template<int MT>
__global__ void __launch_bounds__(256)
gemm_tf32(const float* __restrict__ A, const float* __restrict__ Bp,
          float* __restrict__ Cp,
          int M, int N, int K, int lda, int ldb, int ldc,
          long long sAb, long long sAh, long long sBb, long long sBh,
          long long sCb, long long sCh, int nH,
          const float* __restrict__ bias, const float* __restrict__ resid,
          float alpha, int doGelu, int transB)
{
    extern __shared__ float2 smbuf[];

    int bz = blockIdx.z;
    int bb = bz / nH, hh = bz - bb * nH;
    A  += bb * sAb + hh * sAh;
    Bp += bb * sBb + hh * sBh;
    Cp += bb * sCb + hh * sCh;
    const float* Rp = resid ? (resid + bb * sCb + hh * sCh) : (const float*)0;

    int m0   = blockIdx.y << 7;
    int n0   = blockIdx.x << 7;
    int tid  = threadIdx.x;
    int lane = tid & 31;
    int wid  = tid >> 5;
    int wm   = (MT == 2) ? ((wid & 3) << 5) : (wid << 4);
    int wn   = (MT == 2) ? ((wid >> 2) << 6) : 0;

    float acc[MT][8][4];
    #pragma unroll
    for (int a = 0; a < MT; a++)
        #pragma unroll
        for (int b = 0; b < 8; b++)
            #pragma unroll
            for (int j = 0; j < 4; j++) acc[a][b][j] = 0.f;

    // loader index patterns
    const int la_m = tid >> 2;              // 0..63  (row within half-tile)
    const int la_k = (tid & 3) << 2;        // 0,4,8,12
    const int lb_k = tid >> 5;              // 0..7
    const int lb_n = (tid & 31) << 2;       // 0..124

    float4 ra[2], rb[2];
    const int nk = K >> 4;

    auto LOAD = [&](int k0) {
        #pragma unroll
        for (int j = 0; j < 2; j++) {
            int m = la_m + (j << 6);
            ra[j] = *(const float4*)(A + (size_t)(m0 + m) * lda + (k0 + la_k));
        }
        if (transB) {
            #pragma unroll
            for (int j = 0; j < 2; j++) {
                int n = la_m + (j << 6);
                rb[j] = (n0 + n < N)
                      ? *(const float4*)(Bp + (size_t)(n0 + n) * ldb + (k0 + la_k))
                      : make_float4(0.f, 0.f, 0.f, 0.f);
            }
        } else {
            #pragma unroll
            for (int j = 0; j < 2; j++) {
                int kk = lb_k + (j << 3);
                rb[j] = (n0 + lb_n < N)
                      ? *(const float4*)(Bp + (size_t)(k0 + kk) * ldb + (n0 + lb_n))
                      : make_float4(0.f, 0.f, 0.f, 0.f);
            }
        }
    };

    auto STORE = [&](int s) {
        float2* As = smbuf + s * STG;
        float2* Bs = As + KT * P;
        #pragma unroll
        for (int j = 0; j < 2; j++) {
            int m = la_m + (j << 6);
            float v[4] = {ra[j].x, ra[j].y, ra[j].z, ra[j].w};
            #pragma unroll
            for (int q = 0; q < 4; q++)
                As[(la_k + q) * P + m] = tf32_split2(v[q]);
        }
        if (transB) {
            #pragma unroll
            for (int j = 0; j < 2; j++) {
                int n = la_m + (j << 6);
                float v[4] = {rb[j].x, rb[j].y, rb[j].z, rb[j].w};
                #pragma unroll
                for (int q = 0; q < 4; q++)
                    Bs[(la_k + q) * P + n] = tf32_split2(v[q]);
            }
        } else {
            #pragma unroll
            for (int j = 0; j < 2; j++) {
                int kk = lb_k + (j << 3);
                float v[4] = {rb[j].x, rb[j].y, rb[j].z, rb[j].w};
                #pragma unroll
                for (int q = 0; q < 4; q++)
                    Bs[kk * P + lb_n + q] = tf32_split2(v[q]);
            }
        }
    };

    LOAD(0);
    STORE(0);
    __syncthreads();

    for (int t = 0; t < nk; t++) {
        if (t + 1 < nk) LOAD((t + 1) << 4);

        const float2* As = smbuf + (t & 1) * STG;
        const float2* Bs = As + KT * P;

        #pragma unroll
        for (int kk = 0; kk < 16; kk += 8) {
            int ck = kk + (lane & 3);
            int qd = lane >> 2;
            float2 af[MT][4];
            #pragma unroll
            for (int mt = 0; mt < MT; mt++) {
                int r = wm + (mt << 4) + qd;
                af[mt][0] = As[ck * P + r];
                af[mt][1] = As[ck * P + r + 8];
                af[mt][2] = As[(ck + 4) * P + r];
                af[mt][3] = As[(ck + 4) * P + r + 8];
            }
            float2 bf[8][2];
            #pragma unroll
            for (int nt = 0; nt < 8; nt++) {
                int cn = wn + (nt << 3) + qd;
                bf[nt][0] = Bs[ck * P + cn];
                bf[nt][1] = Bs[(ck + 4) * P + cn];
            }
            #pragma unroll
            for (int mt = 0; mt < MT; mt++) {
                unsigned ah[4], al[4];
                #pragma unroll
                for (int i2 = 0; i2 < 4; i2++) {
                    ah[i2] = __float_as_uint(af[mt][i2].x);
                    al[i2] = __float_as_uint(af[mt][i2].y);
                }
                #pragma unroll
                for (int nt = 0; nt < 8; nt++) {
                    unsigned bh[2] = {__float_as_uint(bf[nt][0].x), __float_as_uint(bf[nt][1].x)};
                    unsigned bl[2] = {__float_as_uint(bf[nt][0].y), __float_as_uint(bf[nt][1].y)};
                    mma_tf32(acc[mt][nt], ah, bh);
                    mma_tf32(acc[mt][nt], ah, bl);
                    mma_tf32(acc[mt][nt], al, bh);
                }
            }
        }

        if (t + 1 < nk) STORE((t + 1) & 1);
        __syncthreads();
    }

    // ---- epilogue ----
    #pragma unroll
    for (int mt = 0; mt < MT; mt++) {
        #pragma unroll
        for (int nt = 0; nt < 8; nt++) {
            int row = m0 + wm + (mt << 4) + (lane >> 2);
            int col = n0 + wn + (nt << 3) + ((lane & 3) << 1);
            #pragma unroll
            for (int j = 0; j < 4; j++) {
                int r = row + ((j & 2) ? 8 : 0);
                int c = col + (j & 1);
                if (c < N) {
                    float v2 = acc[mt][nt][j] * alpha;
                    if (bias) v2 += bias[c];
                    if (doGelu) v2 = 0.5f * v2 * (1.f + erff(v2 * 0.70710678118654752f));
                    if (Rp) v2 += Rp[(size_t)r * ldc + c];
                    Cp[(size_t)r * ldc + c] = v2;
                }
            }
        }
    }
}

// ---------------------------------------------------------------------------
// Pack per-layer Wq/Wk/Wv [C,C] into Wcat [C, 3C]
// ---------------------------------------------------------------------------
__global__ void pack_qkv(const float* __restrict__ Wq, const float* __restrict__ Wk,
                         const float* __restrict__ Wv, float* __restrict__ Wcat)
{
    int i = blockIdx.x * 256 + threadIdx.x;
    if (i < C_ * C_) {
        int k = i / C_, j = i - k * C_;
        Wcat[(size_t)k * C3_ + j]            = Wq[i];
        Wcat[(size_t)k * C3_ + C_ + j]       = Wk[i];
        Wcat[(size_t)k * C3_ + 2 * C_ + j]   = Wv[i];
    }
}

// ---------------------------------------------------------------------------
// LayerNorm (biased variance, eps=1e-5): one block (256 thr) per row
// ---------------------------------------------------------------------------
__global__ void layernorm_k(const float* __restrict__ x, const float* __restrict__ g,
                            const float* __restrict__ b, float* __restrict__ y)
{
    int row = blockIdx.x;
    const float* xr = x + (size_t)row * C_;
    float* yr       = y + (size_t)row * C_;
    int tid = threadIdx.x;
    float s = 0.f, s2 = 0.f;
    for (int c = tid; c < C_; c += 256) { float v = xr[c]; s += v; s2 += v * v; }
    __shared__ float shs[8], shs2[8];
    #pragma unroll
    for (int o = 16; o; o >>= 1) {
        s  += __shfl_xor_sync(0xffffffffu, s,  o);
        s2 += __shfl_xor_sync(0xffffffffu, s2, o);
    }
    if ((tid & 31) == 0) { shs[tid >> 5] = s; shs2[tid >> 5] = s2; }
    __syncthreads();
    float ts = 0.f, ts2 = 0.f;
    #pragma unroll
    for (int i = 0; i < 8; i++) { ts += shs[i]; ts2 += shs2[i]; }
    float mean = ts * (1.f / C_);
    float var  = ts2 * (1.f / C_) - mean * mean;
    float rstd = rsqrtf(var + 1e-5f);
    for (int c = tid; c < C_; c += 256)
        yr[c] = (xr[c] - mean) * rstd * g[c] + b[c];
}

// ---------------------------------------------------------------------------
// Causal softmax in place; row cached in registers (single read, single write)
// ---------------------------------------------------------------------------
__global__ void softmax_causal(float* __restrict__ att)
{
    int row = blockIdx.x;             // b*H*T + h*T + q
    int q   = row & (T_ - 1);
    float* a = att + (size_t)row * T_;
    int len = q + 1;
    int tid = threadIdx.x;
    __shared__ float sh[8];

    float r[4];
    #pragma unroll
    for (int i = 0; i < 4; i++) {
        int c = tid + (i << 8);
        r[i] = (c < len) ? a[c] : -3.0e38f;
    }
    float mx = fmaxf(fmaxf(r[0], r[1]), fmaxf(r[2], r[3]));
    #pragma unroll
    for (int o = 16; o; o >>= 1) mx = fmaxf(mx, __shfl_xor_sync(0xffffffffu, mx, o));
    if ((tid & 31) == 0) sh[tid >> 5] = mx;
    __syncthreads();
    mx = sh[0];
    #pragma unroll
    for (int i = 1; i < 8; i++) mx = fmaxf(mx, sh[i]);
    __syncthreads();

    float s = 0.f;
    #pragma unroll
    for (int i = 0; i < 4; i++) {
        int c = tid + (i << 8);
        r[i] = (c < len) ? expf(r[i] - mx) : 0.f;
        s += r[i];
    }
    #pragma unroll
    for (int o = 16; o; o >>= 1) s += __shfl_xor_sync(0xffffffffu, s, o);
    if ((tid & 31) == 0) sh[tid >> 5] = s;
    __syncthreads();
    float tot = 0.f;
    #pragma unroll
    for (int i = 0; i < 8; i++) tot += sh[i];
    float inv = 1.f / tot;

    #pragma unroll
    for (int i = 0; i < 4; i++) {
        int c = tid + (i << 8);
        a[c] = r[i] * inv;
    }
}

// ---------------------------------------------------------------------------
// Embedding
// ---------------------------------------------------------------------------
__global__ void embed_k(const int* __restrict__ idx, const float* __restrict__ tok,
                        const float* __restrict__ pos, float* __restrict__ x)
{
    int r = blockIdx.x;
    int t = r & (T_ - 1);
    int token = idx[r];
    const float* te = tok + (size_t)token * C_;
    const float* pe = pos + (size_t)t * C_;
    float* xr = x + (size_t)r * C_;
    for (int c = threadIdx.x; c < C_; c += 256) xr[c] = te[c] + pe[c];
}

// ---------------------------------------------------------------------------
// Launch
// ---------------------------------------------------------------------------
extern "C" void kernel_launch(void* const* d_in, const int* in_sizes, int n_in,
                              void* d_out, int out_size)
{
    (void)in_sizes; (void)n_in; (void)out_size;
    const int*   idx = (const int*)d_in[0];
    const float* tok = (const float*)d_in[1];
    const float* pos = (const float*)d_in[2];
    const float* Wq  = (const float*)d_in[3];
    const float* Wk  = (const float*)d_in[4];
    const float* Wv  = (const float*)d_in[5];
    const float* Wp  = (const float*)d_in[6];
    const float* bp  = (const float*)d_in[7];
    const float* g1  = (const float*)d_in[8];
    const float* be1 = (const float*)d_in[9];
    const float* g2  = (const float*)d_in[10];
    const float* be2 = (const float*)d_in[11];
    const float* W1  = (const float*)d_in[12];
    const float* bb1 = (const float*)d_in[13];
    const float* W2  = (const float*)d_in[14];
    const float* bb2 = (const float*)d_in[15];
    const float* gf  = (const float*)d_in[16];
    const float* bf  = (const float*)d_in[17];
    const float* Wh  = (const float*)d_in[18];
    const float* bhd = (const float*)d_in[19];
    float* out = (float*)d_out;

    float *x, *h, *qkv, *o, *a1, *att, *wcat;
    cudaGetSymbolAddress((void**)&x,    g_x);
    cudaGetSymbolAddress((void**)&h,    g_h);
    cudaGetSymbolAddress((void**)&qkv,  g_qkv);
    cudaGetSymbolAddress((void**)&o,    g_o);
    cudaGetSymbolAddress((void**)&a1,   g_a1);
    cudaGetSymbolAddress((void**)&att,  g_att);
    cudaGetSymbolAddress((void**)&wcat, g_wcat);

    cudaFuncSetAttribute((const void*)gemm_tf32<2>,
                         cudaFuncAttributeMaxDynamicSharedMemorySize, (int)SMEM_BYTES);
    cudaFuncSetAttribute((const void*)gemm_tf32<1>,
                         cudaFuncAttributeMaxDynamicSharedMemorySize, (int)SMEM_BYTES);

    const float att_scale = 0.03608439182435161f;  // 768^-0.5 (reference uses full C)

    embed_k<<<BT_, 256>>>(idx, tok, pos, x);

    dim3 gqkv(C3_ / 128, BT_ / 128, 1);
    dim3 gcc (C_  / 128, BT_ / 128, 1);
    dim3 gsc (T_  / 128, T_  / 128, B_ * H_);
    dim3 gav (1,         T_  / 128, B_ * H_);
    dim3 gf1 (C4_ / 128, BT_ / 128, 1);

    for (int l = 0; l < L_; l++) {
        layernorm_k<<<BT_, 256>>>(x, g1 + l * C_, be1 + l * C_, h);

        pack_qkv<<<(C_ * C_ + 255) / 256, 256>>>(Wq + (size_t)l * C_ * C_,
                                                 Wk + (size_t)l * C_ * C_,
                                                 Wv + (size_t)l * C_ * C_, wcat);

        // qkv = h @ Wcat  -> [BT, 3C]
        gemm_tf32<2><<<gqkv, 256, SMEM_BYTES>>>(h, wcat, qkv, BT_, C3_, C_, C_, C3_, C3_,
                                0, 0, 0, 0, 0, 0, 1, (const float*)0, (const float*)0, 1.f, 0, 0);

        // scores: per (b,head) Q[1024,64] @ K^T -> att[1024,1024] (scaled)
        gemm_tf32<2><<<gsc, 256, SMEM_BYTES>>>(qkv, qkv + C_, att, T_, T_, HS_, C3_, C3_, T_,
                                (long long)T_ * C3_, (long long)HS_,
                                (long long)T_ * C3_, (long long)HS_,
                                (long long)H_ * T_ * T_, (long long)T_ * T_, H_,
                                (const float*)0, (const float*)0, att_scale, 0, 1);

        softmax_causal<<<B_ * H_ * T_, 256>>>(att);

        // AV: P[1024,1024] @ V[1024,64] -> o  (MT=1 layout for N=64)
        gemm_tf32<1><<<gav, 256, SMEM_BYTES>>>(att, qkv + 2 * C_, o, T_, HS_, T_, T_, C3_, C_,
                                (long long)H_ * T_ * T_, (long long)T_ * T_,
                                (long long)T_ * C3_, (long long)HS_,
                                (long long)T_ * C_, (long long)HS_, H_,
                                (const float*)0, (const float*)0, 1.f, 0, 0);

        // x = x + o @ Wproj + bproj
        gemm_tf32<2><<<gcc, 256, SMEM_BYTES>>>(o, Wp + (size_t)l * C_ * C_, x, BT_, C_, C_, C_, C_, C_,
                                0, 0, 0, 0, 0, 0, 1, bp + l * C_, x, 1.f, 0, 0);

        layernorm_k<<<BT_, 256>>>(x, g2 + l * C_, be2 + l * C_, h);

        // a1 = gelu(h @ W1 + b1)
        gemm_tf32<2><<<gf1, 256, SMEM_BYTES>>>(h, W1 + (size_t)l * C_ * C4_, a1, BT_, C4_, C_, C_, C4_, C4_,
                                0, 0, 0, 0, 0, 0, 1, bb1 + l * C4_, (const float*)0, 1.f, 1, 0);

        // x = x + a1 @ W2 + b2
        gemm_tf32<2><<<gcc, 256, SMEM_BYTES>>>(a1, W2 + (size_t)l * C4_ * C_, x, BT_, C_, C4_, C4_, C_, C_,
                                0, 0, 0, 0, 0, 0, 1, bb2 + l * C_, x, 1.f, 0, 0);
    }

    layernorm_k<<<BT_, 256>>>(x, gf, bf, h);

    dim3 ghd(V_ / 128, BT_ / 128, 1);
    gemm_tf32<2><<<ghd, 256, SMEM_BYTES>>>(h, Wh, out, BT_, V_, C_, C_, V_, V_,
                            0, 0, 0, 0, 0, 0, 1, bhd, (const float*)0, 1.f, 0, 0);
}